// round 1
// baseline (speedup 1.0000x reference)
#include <cuda_runtime.h>
#include <cuda_bf16.h>

// GRU encoder: B=512, T=128, V=128, E=512, H=512, L=2
// out = [ states[T, L, B, H] , h_final[L, B, H] ]  (h_final == states[T-1])
//
// Strategy (R1 baseline): fused fp32 GRU-cell kernel, one launch per superstep t,
// computing layer0 @ step t and layer1 @ step t-1 concurrently (layer pipeline lag),
// 129 launches total. Hidden states are read from / written to the states region
// of d_out itself, so no scratch is needed.

namespace {

constexpr int B_ = 512;
constexpr int T_ = 128;
constexpr int E_ = 512;
constexpr int H_ = 512;
constexpr int L_ = 2;
constexpr int HG = 3 * H_;   // 1536

constexpr int BT = 64;   // batch tile per CTA
constexpr int JT = 32;   // hidden-unit tile per CTA
constexpr int KT = 32;   // K tile
constexpr int NC = 96;   // 3 gates * JT columns

// smem plan (48KB, exactly at the static limit):
//   phase A (GEMM passes): xs[KT][BT] (2048 f) + ws[KT][NC] (3072 f) = 20KB
//   phase B (gate math)  : sgi[BT][NC] (6144 f) + sgh[BT][NC] (6144 f) = 48KB
// Phase B overlays phase A (accumulators live in registers in between).

__global__ __launch_bounds__(256, 2)
void gru_cell(const int*   __restrict__ input,     // [B, T]
              const float* __restrict__ h0init,    // [L, B, H]
              const float* __restrict__ emb,       // [V, E]
              const float* __restrict__ w_ih,      // [L, 3H, E]
              const float* __restrict__ w_hh,      // [L, 3H, H]
              const float* __restrict__ b_ih,      // [L, 3H]
              const float* __restrict__ b_hh,      // [L, 3H]
              float*       __restrict__ out,
              int t, int write_final)
{
    const int layer = blockIdx.z;
    const int s = (layer == 0) ? t : t - 1;   // which time step this layer computes
    if (s < 0 || s >= T_) return;

    const int jbase = blockIdx.x * JT;
    const int bbase = blockIdx.y * BT;
    const int tid = threadIdx.x;
    const int tx = tid & 15;    // column group (6 cols each)
    const int ty = tid >> 4;    // row group (4 rows each)

    __shared__ float smem[12288];   // 48KB
    float (*xs)[BT]  = (float (*)[BT])(smem);            // [KT][BT]
    float (*ws)[NC]  = (float (*)[NC])(smem + KT * BT);  // [KT][NC]
    float (*sgi)[NC] = (float (*)[NC])(smem);            // [BT][NC]
    float (*sgh)[NC] = (float (*)[NC])(smem + BT * NC);  // [BT][NC]

    const float* wsrc_i = w_ih + (size_t)layer * HG * E_;
    const float* wsrc_h = w_hh + (size_t)layer * HG * H_;

    // x source for the gi pass
    const float* xbase = (layer == 0)
        ? emb
        : (out + (size_t)(s * L_ + 0) * B_ * H_);         // h0 at step s
    // previous hidden state for this layer
    const float* hprev = (s == 0)
        ? (h0init + (size_t)layer * B_ * H_)
        : (out + (size_t)((s - 1) * L_ + layer) * B_ * H_);

    float acc[2][4][6];
    #pragma unroll
    for (int p = 0; p < 2; p++)
        #pragma unroll
        for (int i = 0; i < 4; i++)
            #pragma unroll
            for (int j = 0; j < 6; j++)
                acc[p][i][j] = 0.0f;

    // pass 0: gi = x @ Wi^T ; pass 1: gh = h_prev @ Wh^T   (K = 512 both)
    #pragma unroll
    for (int pass = 0; pass < 2; pass++) {
        const float* wsrc = pass ? wsrc_h : wsrc_i;
        for (int k0 = 0; k0 < 512; k0 += KT) {
            // --- load x tile (transposed: xs[k][b]), 512 float4s ---
            #pragma unroll
            for (int it = 0; it < 2; it++) {
                int idx = tid + it * 256;
                int b   = idx & 63;
                int k4  = idx >> 6;         // 0..7
                const float* rowp;
                if (pass == 0) {
                    if (layer == 0) {
                        int tok = input[(size_t)(bbase + b) * T_ + s];
                        rowp = emb + (size_t)tok * E_;
                    } else {
                        rowp = xbase + (size_t)(bbase + b) * H_;
                    }
                } else {
                    rowp = hprev + (size_t)(bbase + b) * H_;
                }
                float4 v = *(const float4*)(rowp + k0 + k4 * 4);
                xs[k4 * 4 + 0][b] = v.x;
                xs[k4 * 4 + 1][b] = v.y;
                xs[k4 * 4 + 2][b] = v.z;
                xs[k4 * 4 + 3][b] = v.w;
            }
            // --- load W tile (transposed: ws[k][c]), 768 float4s ---
            #pragma unroll
            for (int it = 0; it < 3; it++) {
                int idx = tid + it * 256;
                int c   = idx % 96;
                int k4  = idx / 96;         // 0..7
                int g   = c >> 5;
                int jj  = c & 31;
                int m   = g * H_ + jbase + jj;
                float4 v = *(const float4*)(wsrc + (size_t)m * 512 + k0 + k4 * 4);
                ws[k4 * 4 + 0][c] = v.x;
                ws[k4 * 4 + 1][c] = v.y;
                ws[k4 * 4 + 2][c] = v.z;
                ws[k4 * 4 + 3][c] = v.w;
            }
            __syncthreads();
            #pragma unroll
            for (int k = 0; k < KT; k++) {
                float4 a  = *(const float4*)&xs[k][ty * 4];
                float2 w0 = *(const float2*)&ws[k][tx * 6 + 0];
                float2 w1 = *(const float2*)&ws[k][tx * 6 + 2];
                float2 w2 = *(const float2*)&ws[k][tx * 6 + 4];
                float av[4] = {a.x, a.y, a.z, a.w};
                float wv[6] = {w0.x, w0.y, w1.x, w1.y, w2.x, w2.y};
                #pragma unroll
                for (int i = 0; i < 4; i++)
                    #pragma unroll
                    for (int j = 0; j < 6; j++)
                        acc[pass][i][j] = fmaf(av[i], wv[j], acc[pass][i][j]);
            }
            __syncthreads();
        }
    }

    // --- dump accumulators to smem (overlays the GEMM tiles) ---
    #pragma unroll
    for (int i = 0; i < 4; i++)
        #pragma unroll
        for (int j = 0; j < 6; j++) {
            sgi[ty * 4 + i][tx * 6 + j] = acc[0][i][j];
            sgh[ty * 4 + i][tx * 6 + j] = acc[1][i][j];
        }
    __syncthreads();

    // --- gate math + store ---
    float* hdst = out + (size_t)(s * L_ + layer) * B_ * H_;
    float* fdst = (write_final && s == T_ - 1)
        ? (out + (size_t)T_ * L_ * B_ * H_ + (size_t)layer * B_ * H_)
        : nullptr;
    const float* bi = b_ih + (size_t)layer * HG;
    const float* bh = b_hh + (size_t)layer * HG;

    #pragma unroll
    for (int it = 0; it < 8; it++) {
        int e  = tid + it * 256;
        int jj = e & 31;
        int b  = e >> 5;            // 0..63
        int gb = bbase + b;
        int gj = jbase + jj;
        float gir = sgi[b][jj]      + bi[gj];
        float giz = sgi[b][32 + jj] + bi[H_ + gj];
        float gin = sgi[b][64 + jj] + bi[2 * H_ + gj];
        float ghr = sgh[b][jj]      + bh[gj];
        float ghz = sgh[b][32 + jj] + bh[H_ + gj];
        float ghn = sgh[b][64 + jj] + bh[2 * H_ + gj];
        float hp  = hprev[(size_t)gb * H_ + gj];
        float r = 1.0f / (1.0f + expf(-(gir + ghr)));
        float z = 1.0f / (1.0f + expf(-(giz + ghz)));
        float n = tanhf(gin + r * ghn);
        float h = (1.0f - z) * n + z * hp;
        hdst[(size_t)gb * H_ + gj] = h;
        if (fdst) fdst[(size_t)gb * H_ + gj] = h;
    }
}

} // namespace

extern "C" void kernel_launch(void* const* d_in, const int* in_sizes, int n_in,
                              void* d_out, int out_size) {
    const int*   input = (const int*)  d_in[0];
    const float* h0    = (const float*)d_in[1];
    const float* emb   = (const float*)d_in[2];
    const float* w_ih  = (const float*)d_in[3];
    const float* w_hh  = (const float*)d_in[4];
    const float* b_ih  = (const float*)d_in[5];
    const float* b_hh  = (const float*)d_in[6];
    float* out = (float*)d_out;

    // Write h_final region only if the output buffer includes it.
    const long long states_elems = (long long)T_ * L_ * B_ * H_;
    const int write_final = ((long long)out_size >= states_elems + (long long)L_ * B_ * H_) ? 1 : 0;

    dim3 grid(H_ / JT, B_ / BT, L_);   // (16, 8, 2)
    for (int t = 0; t <= T_; t++) {    // 129 supersteps (layer pipeline lag of 1)
        gru_cell<<<grid, 256>>>(input, h0, emb, w_ih, w_hh, b_ih, b_hh, out, t, write_final);
    }
}